// round 13
// baseline (speedup 1.0000x reference)
#include <cuda_runtime.h>
#include <cuda_bf16.h>

// Problem constants (B=2, H=8, S=256, D=64)
#define BATCH 2
#define NHEAD 8
#define SEQ   256
#define DIM   64

// 256-bit (v8) global loads — sm_100a+/sm_103a feature.
__device__ __forceinline__ void ldg_v8(const float* p, float r[8]) {
    asm volatile("ld.global.v8.f32 {%0,%1,%2,%3,%4,%5,%6,%7}, [%8];"
        : "=f"(r[0]), "=f"(r[1]), "=f"(r[2]), "=f"(r[3]),
          "=f"(r[4]), "=f"(r[5]), "=f"(r[6]), "=f"(r[7])
        : "l"(p));
}
__device__ __forceinline__ void ldg_cs_v8(const float* p, float r[8]) {
    asm volatile("ld.global.cs.v8.f32 {%0,%1,%2,%3,%4,%5,%6,%7}, [%8];"
        : "=f"(r[0]), "=f"(r[1]), "=f"(r[2]), "=f"(r[3]),
          "=f"(r[4]), "=f"(r[5]), "=f"(r[6]), "=f"(r[7])
        : "l"(p));
}

// Fused structure-attention kernel. 128 threads/block (4 warps), 8 CTAs/SM,
// 64 regs/thread, grid = B*H*S (one CTA per query row) — the proven config,
// now with 256-bit loads: 2x bytes per LDG at the same instruction count.
//
// Warp lane split: sub = lane&7 owns d-range [8*sub, 8*sub+8),
//                  quarter = lane>>3 selects one of 4 k-rows per iteration.
// Each warp owns 64 k-rows: k in [warp*64, warp*64+64).
__global__ __launch_bounds__(128, 8) void attn_struct_kernel(
    const float* __restrict__ q_,     // [B,H,S,D]
    const float* __restrict__ k_,     // [B,H,S,D]
    const float* __restrict__ v_,     // [B,H,S,D]
    const float* __restrict__ ks_,    // [B,H,S,S,D]
    const float* __restrict__ vs_,    // [B,H,S,S,D]
    const float* __restrict__ mask_,  // [B,S]
    float* __restrict__ out_,         // [B,H,S,D]
    float* __restrict__ attn_)        // [B,H,S,S]
{
    const int row  = blockIdx.x;         // (b*H + h)*S + q
    const int qidx = row & (SEQ - 1);
    const int bh   = row >> 8;           // b*H + h
    const int b    = bh / NHEAD;

    const int tid  = threadIdx.x;        // 0..127
    const int lane = tid & 31;
    const int warp = tid >> 5;           // 0..3
    const int sub  = lane & 7;           // d/8 slot
    const int quarter = lane >> 3;       // which of 4 k-rows

    __shared__ float sh_scores[SEQ];     // scores, then e[k]
    __shared__ float sh_red[4][DIM];
    __shared__ float sh_max[4];
    __shared__ float sh_sum[4];
    __shared__ float sh_q[DIM];

    // ---- load q row; each lane keeps its 8 q components ----
    if (tid < DIM) sh_q[tid] = q_[(size_t)row * DIM + tid];
    __syncthreads();
    float qv[8];
    #pragma unroll
    for (int j = 0; j < 8; ++j) qv[j] = sh_q[sub * 8 + j];

    // ---- Phase B: base scores q.key[k] (L2-hot, compact burst) ----
    // Same thread writes and later accumulates sh_scores[k]; no barrier
    // needed between phases B and C.
    {
        const float* krow = k_ + ((size_t)bh * SEQ + warp * 64 + quarter) * DIM + sub * 8;
        #pragma unroll 4
        for (int i = 0; i < 16; ++i) {
            const int k = warp * 64 + i * 4 + quarter;
            float c[8];
            ldg_v8(krow + (size_t)i * 4 * DIM, c);
            float s = c[0]*qv[0] + c[1]*qv[1] + c[2]*qv[2] + c[3]*qv[3]
                    + c[4]*qv[4] + c[5]*qv[5] + c[6]*qv[6] + c[7]*qv[7];
            #pragma unroll
            for (int off = 4; off >= 1; off >>= 1)
                s += __shfl_xor_sync(0xffffffffu, s, off);
            if (sub == 0) sh_scores[k] = s;
        }
    }

    // ---- Phase C: pure ks DRAM stream (v8, evict-first), accumulate ----
    {
        const float* ksrow = ks_ + ((size_t)row * SEQ + warp * 64 + quarter) * DIM + sub * 8;
        #pragma unroll 4
        for (int i = 0; i < 16; ++i) {
            const int k = warp * 64 + i * 4 + quarter;
            float a[8];
            ldg_cs_v8(ksrow + (size_t)i * 4 * DIM, a);
            float s = a[0]*qv[0] + a[1]*qv[1] + a[2]*qv[2] + a[3]*qv[3]
                    + a[4]*qv[4] + a[5]*qv[5] + a[6]*qv[6] + a[7]*qv[7];
            #pragma unroll
            for (int off = 4; off >= 1; off >>= 1)
                s += __shfl_xor_sync(0xffffffffu, s, off);
            if (sub == 0) sh_scores[k] += s;
        }
    }
    __syncthreads();

    // ---- softmax (single-barrier reductions) ----
    // mask indexed by q (faithful to reference broadcast [B,1,Sq,1]).
    const float mval = (1.0f - mask_[b * SEQ + qidx]) * -100000.0f;
    float sc0 = (sh_scores[tid]       + mval) * 0.125f;   // 1/sqrt(64)
    float sc1 = (sh_scores[tid + 128] + mval) * 0.125f;

    float m = fmaxf(sc0, sc1);
    #pragma unroll
    for (int off = 16; off >= 1; off >>= 1)
        m = fmaxf(m, __shfl_xor_sync(0xffffffffu, m, off));
    if (lane == 0) sh_max[warp] = m;
    __syncthreads();
    const float rowmax = fmaxf(fmaxf(sh_max[0], sh_max[1]),
                               fmaxf(sh_max[2], sh_max[3]));

    const float e0 = __expf(sc0 - rowmax);
    const float e1 = __expf(sc1 - rowmax);

    // publish e[k] and warp sum partials under ONE barrier
    sh_scores[tid]       = e0;
    sh_scores[tid + 128] = e1;
    float s = e0 + e1;
    #pragma unroll
    for (int off = 16; off >= 1; off >>= 1)
        s += __shfl_xor_sync(0xffffffffu, s, off);
    if (lane == 0) sh_sum[warp] = s;
    __syncthreads();

    const float inv_sum = 1.0f / (sh_sum[0] + sh_sum[1] + sh_sum[2] + sh_sum[3]);

    // attn output straight from registers (coalesced, evict-first)
    __stcs(attn_ + (size_t)row * SEQ + tid,       e0 * inv_sum);
    __stcs(attn_ + (size_t)row * SEQ + tid + 128, e1 * inv_sum);

    // ---- Pass 2 ----
    float acc[8];
    #pragma unroll
    for (int j = 0; j < 8; ++j) acc[j] = 0.0f;

    // Phase E: acc = sum_k e[k]*val[k,d]   (val L2-hot, compact burst)
    {
        const float* vbase = v_ + ((size_t)bh * SEQ + warp * 64 + quarter) * DIM + sub * 8;
        #pragma unroll 4
        for (int i = 0; i < 16; ++i) {
            const int k = warp * 64 + i * 4 + quarter;
            const float a = sh_scores[k];
            float vv[8];
            ldg_v8(vbase + (size_t)i * 4 * DIM, vv);
            #pragma unroll
            for (int j = 0; j < 8; ++j) acc[j] = fmaf(a, vv[j], acc[j]);
        }
    }

    // Phase F: pure vs DRAM stream (v8, evict-first), accumulate
    {
        const float* vsbase = vs_ + ((size_t)row * SEQ + warp * 64 + quarter) * DIM + sub * 8;
        #pragma unroll 4
        for (int i = 0; i < 16; ++i) {
            const int k = warp * 64 + i * 4 + quarter;
            const float a = sh_scores[k];
            float sv[8];
            ldg_cs_v8(vsbase + (size_t)i * 4 * DIM, sv);
            #pragma unroll
            for (int j = 0; j < 8; ++j) acc[j] = fmaf(a, sv[j], acc[j]);
        }
    }

    // fold the four k-quarters (lanes with equal sub share a d-range)
    #pragma unroll
    for (int j = 0; j < 8; ++j) {
        acc[j] += __shfl_xor_sync(0xffffffffu, acc[j], 8);
        acc[j] += __shfl_xor_sync(0xffffffffu, acc[j], 16);
    }
    if (quarter == 0) {
        #pragma unroll
        for (int j = 0; j < 8; ++j)
            sh_red[warp][sub * 8 + j] = acc[j] * inv_sum;
    }
    __syncthreads();

    if (tid < DIM) {
        float r = sh_red[0][tid] + sh_red[1][tid]
                + sh_red[2][tid] + sh_red[3][tid];
        __stcs(out_ + (size_t)row * DIM + tid, r);
    }
}

extern "C" void kernel_launch(void* const* d_in, const int* in_sizes, int n_in,
                              void* d_out, int out_size) {
    const float* q    = (const float*)d_in[0];
    const float* k    = (const float*)d_in[1];
    const float* v    = (const float*)d_in[2];
    const float* ks   = (const float*)d_in[3];
    const float* vs   = (const float*)d_in[4];
    const float* mask = (const float*)d_in[5];

    float* out  = (float*)d_out;                              // [B,H,S,D]
    float* attn = out + (size_t)BATCH * NHEAD * SEQ * DIM;    // [B,H,S,S]

    const int nrows = BATCH * NHEAD * SEQ;   // 4096
    attn_struct_kernel<<<nrows, 128>>>(q, k, v, ks, vs, mask, out, attn);
}